// round 1
// baseline (speedup 1.0000x reference)
#include <cuda_runtime.h>
#include <math.h>

#define BB 8
#define SS 2048
#define DD 1024
#define HH 64

// Scratch for Q, K, V projections: [B*S, H] each (4 MB each).
__device__ float g_Q[BB * SS * HH];
__device__ float g_K[BB * SS * HH];
__device__ float g_V[BB * SS * HH];

// ---------------------------------------------------------------------------
// Kernel 1: fused QKV projection.
// GEMM: [16384 x 1024] x [1024 x 64] -> three outputs.
// Block: 256 threads, tile 64 rows x 64 cols (full H), BK = 32.
// Each thread: 4x4 microtile per output (48 fp32 accumulators).
// ---------------------------------------------------------------------------
__global__ __launch_bounds__(256) void qkv_kernel(
    const float* __restrict__ x,
    const float* __restrict__ Wq,
    const float* __restrict__ Wk,
    const float* __restrict__ Wv)
{
    __shared__ float xs[64][33];   // padded: conflict-free column reads
    __shared__ float wq[32][64];
    __shared__ float wk[32][64];
    __shared__ float wv[32][64];

    const int tid = threadIdx.x;
    const int tx = tid & 15;       // col group (16)
    const int ty = tid >> 4;       // row group (16)
    const int row0 = blockIdx.x * 64;

    float aQ[4][4] = {}, aK[4][4] = {}, aV[4][4] = {};

    for (int k0 = 0; k0 < DD; k0 += 32) {
        // Load x tile 64x32 (512 float4, 2 per thread), coalesced.
        #pragma unroll
        for (int i = 0; i < 2; i++) {
            int idx = tid + i * 256;       // 0..511
            int r = idx >> 3;              // 8 float4 per row
            int c = (idx & 7) << 2;
            float4 v = *(const float4*)(x + (long)(row0 + r) * DD + k0 + c);
            xs[r][c + 0] = v.x; xs[r][c + 1] = v.y;
            xs[r][c + 2] = v.z; xs[r][c + 3] = v.w;
        }
        // Load weight tiles 32x64 (512 float4 each, 2 per thread each).
        #pragma unroll
        for (int i = 0; i < 2; i++) {
            int idx = tid + i * 256;
            int r = idx >> 4;              // 16 float4 per row
            int c = (idx & 15) << 2;
            long g = (long)(k0 + r) * HH + c;
            *(float4*)&wq[r][c] = *(const float4*)(Wq + g);
            *(float4*)&wk[r][c] = *(const float4*)(Wk + g);
            *(float4*)&wv[r][c] = *(const float4*)(Wv + g);
        }
        __syncthreads();

        #pragma unroll
        for (int kk = 0; kk < 32; kk++) {
            float a[4];
            #pragma unroll
            for (int i = 0; i < 4; i++) a[i] = xs[ty * 4 + i][kk];
            float4 bq = *(const float4*)&wq[kk][tx * 4];
            float4 bk = *(const float4*)&wk[kk][tx * 4];
            float4 bv = *(const float4*)&wv[kk][tx * 4];
            #pragma unroll
            for (int i = 0; i < 4; i++) {
                aQ[i][0] += a[i] * bq.x; aQ[i][1] += a[i] * bq.y;
                aQ[i][2] += a[i] * bq.z; aQ[i][3] += a[i] * bq.w;
                aK[i][0] += a[i] * bk.x; aK[i][1] += a[i] * bk.y;
                aK[i][2] += a[i] * bk.z; aK[i][3] += a[i] * bk.w;
                aV[i][0] += a[i] * bv.x; aV[i][1] += a[i] * bv.y;
                aV[i][2] += a[i] * bv.z; aV[i][3] += a[i] * bv.w;
            }
        }
        __syncthreads();
    }

    #pragma unroll
    for (int i = 0; i < 4; i++) {
        long r = (long)(row0 + ty * 4 + i) * HH + tx * 4;
        *(float4*)&g_Q[r] = make_float4(aQ[i][0], aQ[i][1], aQ[i][2], aQ[i][3]);
        *(float4*)&g_K[r] = make_float4(aK[i][0], aK[i][1], aK[i][2], aK[i][3]);
        *(float4*)&g_V[r] = make_float4(aV[i][0], aV[i][1], aV[i][2], aV[i][3]);
    }
}

// ---------------------------------------------------------------------------
// Kernel 2: causal flash attention (online softmax).
// Grid: (S/64, B). Block: 256 threads. 64 queries x 64 keys per step.
// smem: qs[64][65] + ks[64][65] + ps[64][65] + vs[64][64] = 66304 B (dynamic).
// ---------------------------------------------------------------------------
#define Q_PITCH 65
#define ATTN_SMEM_BYTES ((64 * 65 * 3 + 64 * 64) * 4)

__global__ __launch_bounds__(256) void attn_kernel(float* __restrict__ Out)
{
    extern __shared__ float sm[];
    float* qs = sm;                      // 64 x 65
    float* ks = sm + 64 * 65;            // 64 x 65
    float* ps = sm + 2 * 64 * 65;        // 64 x 65
    float* vs = sm + 3 * 64 * 65;        // 64 x 64

    const int tid = threadIdx.x;
    const int tx = tid & 15;
    const int ty = tid >> 4;
    const int qb = blockIdx.x;   // query block (0..31)
    const int b  = blockIdx.y;   // batch

    const float* Qg = g_Q + ((long)b * SS + qb * 64) * HH;
    const float* Kg = g_K + (long)b * SS * HH;
    const float* Vg = g_V + (long)b * SS * HH;

    // Load Q tile (64x64): 1024 float4, 4 per thread.
    #pragma unroll
    for (int i = 0; i < 4; i++) {
        int idx = tid + i * 256;
        int r = idx >> 4;
        int c = (idx & 15) << 2;
        float4 v = *(const float4*)(Qg + (long)r * HH + c);
        qs[r * Q_PITCH + c + 0] = v.x; qs[r * Q_PITCH + c + 1] = v.y;
        qs[r * Q_PITCH + c + 2] = v.z; qs[r * Q_PITCH + c + 3] = v.w;
    }

    float m[4], l[4], o[4][4] = {};
    #pragma unroll
    for (int i = 0; i < 4; i++) { m[i] = -INFINITY; l[i] = 0.0f; }

    const float scale = 0.125f;   // 1/sqrt(64)

    for (int kb = 0; kb <= qb; kb++) {
        // Load K and V blocks (each 64x64).
        #pragma unroll
        for (int i = 0; i < 4; i++) {
            int idx = tid + i * 256;
            int r = idx >> 4;
            int c = (idx & 15) << 2;
            long g = (long)(kb * 64 + r) * HH + c;
            float4 kv = *(const float4*)(Kg + g);
            ks[r * Q_PITCH + c + 0] = kv.x; ks[r * Q_PITCH + c + 1] = kv.y;
            ks[r * Q_PITCH + c + 2] = kv.z; ks[r * Q_PITCH + c + 3] = kv.w;
            *(float4*)&vs[r * 64 + c] = *(const float4*)(Vg + g);
        }
        __syncthreads();

        // S = Q K^T (64x64), 4x4 per thread.
        float s[4][4] = {};
        #pragma unroll
        for (int h = 0; h < 64; h++) {
            float a[4], bb[4];
            #pragma unroll
            for (int i = 0; i < 4; i++) a[i] = qs[(ty * 4 + i) * Q_PITCH + h];
            #pragma unroll
            for (int j = 0; j < 4; j++) bb[j] = ks[(tx * 4 + j) * Q_PITCH + h];
            #pragma unroll
            for (int i = 0; i < 4; i++)
                #pragma unroll
                for (int j = 0; j < 4; j++)
                    s[i][j] += a[i] * bb[j];
        }

        // Scale + causal mask (only diagonal block needs it).
        #pragma unroll
        for (int i = 0; i < 4; i++)
            #pragma unroll
            for (int j = 0; j < 4; j++) {
                s[i][j] *= scale;
                if (kb == qb && (tx * 4 + j) > (ty * 4 + i))
                    s[i][j] = -INFINITY;
            }

        // Row max across the 16 threads of each row group.
        float rmax[4];
        #pragma unroll
        for (int i = 0; i < 4; i++) {
            rmax[i] = fmaxf(fmaxf(s[i][0], s[i][1]), fmaxf(s[i][2], s[i][3]));
        }
        #pragma unroll
        for (int off = 1; off < 16; off <<= 1)
            #pragma unroll
            for (int i = 0; i < 4; i++)
                rmax[i] = fmaxf(rmax[i], __shfl_xor_sync(0xffffffffu, rmax[i], off));

        // Online softmax update.
        float rsum[4] = {};
        #pragma unroll
        for (int i = 0; i < 4; i++) {
            float nm = fmaxf(m[i], rmax[i]);
            float alpha = __expf(m[i] - nm);
            m[i] = nm;
            l[i] *= alpha;
            #pragma unroll
            for (int j = 0; j < 4; j++) o[i][j] *= alpha;
            #pragma unroll
            for (int j = 0; j < 4; j++) {
                float p = __expf(s[i][j] - nm);
                ps[(ty * 4 + i) * Q_PITCH + tx * 4 + j] = p;
                rsum[i] += p;
            }
        }
        #pragma unroll
        for (int off = 1; off < 16; off <<= 1)
            #pragma unroll
            for (int i = 0; i < 4; i++)
                rsum[i] += __shfl_xor_sync(0xffffffffu, rsum[i], off);
        #pragma unroll
        for (int i = 0; i < 4; i++) l[i] += rsum[i];

        __syncthreads();   // ps complete before PV

        // O += P V.
        #pragma unroll
        for (int k = 0; k < 64; k++) {
            float a[4];
            #pragma unroll
            for (int i = 0; i < 4; i++) a[i] = ps[(ty * 4 + i) * Q_PITCH + k];
            float4 bv = *(const float4*)&vs[k * 64 + tx * 4];
            #pragma unroll
            for (int i = 0; i < 4; i++) {
                o[i][0] += a[i] * bv.x; o[i][1] += a[i] * bv.y;
                o[i][2] += a[i] * bv.z; o[i][3] += a[i] * bv.w;
            }
        }
        __syncthreads();   // before ks/vs are overwritten next iter
    }

    // Normalize and write out.
    float* Og = Out + ((long)b * SS + qb * 64) * HH;
    #pragma unroll
    for (int i = 0; i < 4; i++) {
        float inv = 1.0f / l[i];
        float4 v = make_float4(o[i][0] * inv, o[i][1] * inv,
                               o[i][2] * inv, o[i][3] * inv);
        *(float4*)(Og + (long)(ty * 4 + i) * HH + tx * 4) = v;
    }
}

// ---------------------------------------------------------------------------
extern "C" void kernel_launch(void* const* d_in, const int* in_sizes, int n_in,
                              void* d_out, int out_size)
{
    const float* x  = (const float*)d_in[0];
    const float* Wq = (const float*)d_in[1];
    const float* Wk = (const float*)d_in[2];
    const float* Wv = (const float*)d_in[3];
    float* out = (float*)d_out;

    (void)in_sizes; (void)n_in; (void)out_size;

    // Capture-safe (not a stream op, not an allocation); idempotent.
    cudaFuncSetAttribute(attn_kernel,
                         cudaFuncAttributeMaxDynamicSharedMemorySize,
                         ATTN_SMEM_BYTES);

    qkv_kernel<<<(BB * SS) / 64, 256>>>(x, Wq, Wk, Wv);
    attn_kernel<<<dim3(SS / 64, BB), 256, ATTN_SMEM_BYTES>>>(out);
}

// round 5
// speedup vs baseline: 1.2108x; 1.2108x over previous
#include <cuda_runtime.h>
#include <cuda_bf16.h>
#include <math.h>
#include <stdint.h>

#define BB 8
#define SS 2048
#define DD 1024
#define HH 64

// Scratch: Q,K,V projections [B*S, H] fp32; split weights [192][1024] bf16 hi/lo.
__device__ float g_Q[BB * SS * HH];
__device__ float g_K[BB * SS * HH];
__device__ float g_V[BB * SS * HH];
__device__ __nv_bfloat16 g_Bh[192 * 1024];
__device__ __nv_bfloat16 g_Bl[192 * 1024];

__device__ __forceinline__ uint32_t pack_bf2(float a, float b) {
    __nv_bfloat16 x = __float2bfloat16(a), y = __float2bfloat16(b);
    unsigned short xa = *(unsigned short*)&x, yb = *(unsigned short*)&y;
    return (uint32_t)xa | ((uint32_t)yb << 16);
}

// ---------------------------------------------------------------------------
// Kernel 0: split weights W[k][n] fp32 -> g_Bh/g_Bl[n_global][k] bf16.
// n_global = m*64 + n  (m: 0=Q 1=K 2=V).  [n][k] layout = col-major B for mma.
// ---------------------------------------------------------------------------
__global__ void prep_w(const float* __restrict__ Wq,
                       const float* __restrict__ Wk,
                       const float* __restrict__ Wv)
{
    int i = blockIdx.x * blockDim.x + threadIdx.x;   // 0 .. 192*1024-1
    int n = i >> 10;
    int k = i & 1023;
    int m = n >> 6;
    int col = n & 63;
    const float* W = (m == 0) ? Wq : (m == 1) ? Wk : Wv;
    float w = W[k * 64 + col];
    __nv_bfloat16 h = __float2bfloat16(w);
    float lo = w - __bfloat162float(h);
    g_Bh[(size_t)n * 1024 + k] = h;
    g_Bl[(size_t)n * 1024 + k] = __float2bfloat16(lo);
}

// ---------------------------------------------------------------------------
// Kernel 1: QKV projection via mma.sync.m16n8k16 (bf16 in, fp32 acc),
// 3-term hi/lo split:  C = Ah*Bh + Ah*Bl + Al*Bh   (~fp32 accuracy).
// CTA: 256 threads, tile M=128 x N=192, K-chunk 32.
// Warp grid 4(M) x 2(N): warp tile 32 x 96 = 2 m-tiles x 12 n-tiles.
// NOTE: smem pitch 36 bf16 = 72 B -> rows are only 8-byte aligned; all smem
// stores must be <= 8 bytes wide (uint2). A uint4 store here traps.
// ---------------------------------------------------------------------------
#define APITCH 36   // bf16 units per row (72 B) — low-conflict fragment LDS
#define BPITCH 36

__device__ __forceinline__ void mma_bf16(float c[4],
                                         uint32_t a0, uint32_t a1, uint32_t a2, uint32_t a3,
                                         uint32_t b0, uint32_t b1) {
    asm volatile(
        "mma.sync.aligned.m16n8k16.row.col.f32.bf16.bf16.f32 "
        "{%0,%1,%2,%3}, {%4,%5,%6,%7}, {%8,%9}, {%0,%1,%2,%3};"
        : "+f"(c[0]), "+f"(c[1]), "+f"(c[2]), "+f"(c[3])
        : "r"(a0), "r"(a1), "r"(a2), "r"(a3), "r"(b0), "r"(b1));
}

__device__ __forceinline__ uint32_t lds32(const __nv_bfloat16* p) {
    return *(const uint32_t*)p;
}

__global__ __launch_bounds__(256) void qkv_mma(const float* __restrict__ x)
{
    __shared__ __align__(16) __nv_bfloat16 Ah[128 * APITCH];
    __shared__ __align__(16) __nv_bfloat16 Al[128 * APITCH];
    __shared__ __align__(16) __nv_bfloat16 Bh[192 * BPITCH];
    __shared__ __align__(16) __nv_bfloat16 Bl[192 * BPITCH];

    const int tid = threadIdx.x;
    const int wid = tid >> 5;
    const int lane = tid & 31;
    const int grow = lane >> 2;     // 0..7
    const int tg = lane & 3;        // 0..3
    const int warp_m = wid & 3;     // 0..3 -> rows 32*warp_m
    const int warp_n = wid >> 2;    // 0..1 -> cols 96*warp_n
    const int row0 = blockIdx.x * 128;

    float acc[2][12][4] = {};

    for (int k0 = 0; k0 < DD; k0 += 32) {
        // ---- A: load x fp32 [128 x 32], split hi/lo, store bf16 smem (uint2, 8B).
        #pragma unroll
        for (int i = 0; i < 4; i++) {
            int idx = tid + (i << 8);        // 0..1023 float4 slots
            int r = idx >> 3;                // 8 float4 per row
            int c4 = idx & 7;
            float4 f = *(const float4*)(x + (size_t)(row0 + r) * DD + k0 + c4 * 4);
            uint32_t h01 = pack_bf2(f.x, f.y);
            uint32_t h23 = pack_bf2(f.z, f.w);
            float lx = f.x - __bfloat162float(__float2bfloat16(f.x));
            float ly = f.y - __bfloat162float(__float2bfloat16(f.y));
            float lz = f.z - __bfloat162float(__float2bfloat16(f.z));
            float lw = f.w - __bfloat162float(__float2bfloat16(f.w));
            uint32_t l01 = pack_bf2(lx, ly);
            uint32_t l23 = pack_bf2(lz, lw);
            int off = r * APITCH + c4 * 4;   // byte off = r*72 + c4*8 (8B-aligned)
            *(uint2*)&Ah[off] = make_uint2(h01, h23);
            *(uint2*)&Al[off] = make_uint2(l01, l23);
        }
        // ---- B: copy g_Bh/g_Bl chunk [192 x 32] bf16 to smem.
        // Global read is uint4 (16B-aligned in gmem); smem stores are 2x uint2
        // because rows at pitch 72 B are only 8B-aligned.
        #pragma unroll
        for (int i = 0; i < 3; i++) {
            int idx = tid + (i << 8);        // 0..767
            int r = idx >> 2;                // 4 uint4 per row
            int q = idx & 3;
            int off = r * BPITCH + q * 8;    // byte off = r*72 + q*16 (8B-aligned)
            uint4 vh = *(const uint4*)(g_Bh + (size_t)r * 1024 + k0 + q * 8);
            uint4 vl = *(const uint4*)(g_Bl + (size_t)r * 1024 + k0 + q * 8);
            *(uint2*)&Bh[off]     = make_uint2(vh.x, vh.y);
            *(uint2*)&Bh[off + 4] = make_uint2(vh.z, vh.w);
            *(uint2*)&Bl[off]     = make_uint2(vl.x, vl.y);
            *(uint2*)&Bl[off + 4] = make_uint2(vl.z, vl.w);
        }
        __syncthreads();

        #pragma unroll
        for (int ks = 0; ks < 2; ks++) {
            const int kofs = ks * 16 + tg * 2;
            // A fragments for 2 m-tiles (hi and lo).
            uint32_t ah[2][4], al[2][4];
            #pragma unroll
            for (int mt = 0; mt < 2; mt++) {
                int rb = (warp_m * 32 + mt * 16 + grow) * APITCH + kofs;
                ah[mt][0] = lds32(Ah + rb);
                ah[mt][1] = lds32(Ah + rb + 8 * APITCH);
                ah[mt][2] = lds32(Ah + rb + 8);
                ah[mt][3] = lds32(Ah + rb + 8 * APITCH + 8);
                al[mt][0] = lds32(Al + rb);
                al[mt][1] = lds32(Al + rb + 8 * APITCH);
                al[mt][2] = lds32(Al + rb + 8);
                al[mt][3] = lds32(Al + rb + 8 * APITCH + 8);
            }
            #pragma unroll
            for (int nt = 0; nt < 12; nt++) {
                int cb = (warp_n * 96 + nt * 8 + grow) * BPITCH + kofs;
                uint32_t bh0 = lds32(Bh + cb);
                uint32_t bh1 = lds32(Bh + cb + 8);
                uint32_t bl0 = lds32(Bl + cb);
                uint32_t bl1 = lds32(Bl + cb + 8);
                #pragma unroll
                for (int mt = 0; mt < 2; mt++) {
                    mma_bf16(acc[mt][nt], ah[mt][0], ah[mt][1], ah[mt][2], ah[mt][3], bh0, bh1);
                    mma_bf16(acc[mt][nt], ah[mt][0], ah[mt][1], ah[mt][2], ah[mt][3], bl0, bl1);
                    mma_bf16(acc[mt][nt], al[mt][0], al[mt][1], al[mt][2], al[mt][3], bh0, bh1);
                }
            }
        }
        __syncthreads();
    }

    // ---- Epilogue: acc -> g_Q / g_K / g_V (fp32, [row][64]).
    #pragma unroll
    for (int mt = 0; mt < 2; mt++) {
        int r = row0 + warp_m * 32 + mt * 16 + grow;
        #pragma unroll
        for (int nt = 0; nt < 12; nt++) {
            int col = warp_n * 96 + nt * 8 + tg * 2;
            int mat = col >> 6;
            int c = col & 63;
            float* dst = (mat == 0) ? g_Q : (mat == 1) ? g_K : g_V;
            *(float2*)(dst + (size_t)r * 64 + c) =
                make_float2(acc[mt][nt][0], acc[mt][nt][1]);
            *(float2*)(dst + (size_t)(r + 8) * 64 + c) =
                make_float2(acc[mt][nt][2], acc[mt][nt][3]);
        }
    }
}

// ---------------------------------------------------------------------------
// Kernel 2: causal flash attention (R1 version — proven correct, 218us).
// ---------------------------------------------------------------------------
#define Q_PITCH 65
#define ATTN_SMEM_BYTES ((64 * 65 * 3 + 64 * 64) * 4)

__global__ __launch_bounds__(256) void attn_kernel(float* __restrict__ Out)
{
    extern __shared__ float sm[];
    float* qs = sm;                      // 64 x 65
    float* ks = sm + 64 * 65;            // 64 x 65
    float* ps = sm + 2 * 64 * 65;        // 64 x 65
    float* vs = sm + 3 * 64 * 65;        // 64 x 64

    const int tid = threadIdx.x;
    const int tx = tid & 15;
    const int ty = tid >> 4;
    const int qb = blockIdx.x;
    const int b  = blockIdx.y;

    const float* Qg = g_Q + ((size_t)b * SS + qb * 64) * HH;
    const float* Kg = g_K + (size_t)b * SS * HH;
    const float* Vg = g_V + (size_t)b * SS * HH;

    #pragma unroll
    for (int i = 0; i < 4; i++) {
        int idx = tid + i * 256;
        int r = idx >> 4;
        int c = (idx & 15) << 2;
        float4 v = *(const float4*)(Qg + (size_t)r * HH + c);
        qs[r * Q_PITCH + c + 0] = v.x; qs[r * Q_PITCH + c + 1] = v.y;
        qs[r * Q_PITCH + c + 2] = v.z; qs[r * Q_PITCH + c + 3] = v.w;
    }

    float m[4], l[4], o[4][4] = {};
    #pragma unroll
    for (int i = 0; i < 4; i++) { m[i] = -INFINITY; l[i] = 0.0f; }

    const float scale = 0.125f;

    for (int kb = 0; kb <= qb; kb++) {
        #pragma unroll
        for (int i = 0; i < 4; i++) {
            int idx = tid + i * 256;
            int r = idx >> 4;
            int c = (idx & 15) << 2;
            size_t g = (size_t)(kb * 64 + r) * HH + c;
            float4 kv = *(const float4*)(Kg + g);
            ks[r * Q_PITCH + c + 0] = kv.x; ks[r * Q_PITCH + c + 1] = kv.y;
            ks[r * Q_PITCH + c + 2] = kv.z; ks[r * Q_PITCH + c + 3] = kv.w;
            *(float4*)&vs[r * 64 + c] = *(const float4*)(Vg + g);
        }
        __syncthreads();

        float s[4][4] = {};
        #pragma unroll
        for (int h = 0; h < 64; h++) {
            float a[4], bb[4];
            #pragma unroll
            for (int i = 0; i < 4; i++) a[i] = qs[(ty * 4 + i) * Q_PITCH + h];
            #pragma unroll
            for (int j = 0; j < 4; j++) bb[j] = ks[(tx * 4 + j) * Q_PITCH + h];
            #pragma unroll
            for (int i = 0; i < 4; i++)
                #pragma unroll
                for (int j = 0; j < 4; j++)
                    s[i][j] += a[i] * bb[j];
        }

        #pragma unroll
        for (int i = 0; i < 4; i++)
            #pragma unroll
            for (int j = 0; j < 4; j++) {
                s[i][j] *= scale;
                if (kb == qb && (tx * 4 + j) > (ty * 4 + i))
                    s[i][j] = -INFINITY;
            }

        float rmax[4];
        #pragma unroll
        for (int i = 0; i < 4; i++)
            rmax[i] = fmaxf(fmaxf(s[i][0], s[i][1]), fmaxf(s[i][2], s[i][3]));
        #pragma unroll
        for (int off = 1; off < 16; off <<= 1)
            #pragma unroll
            for (int i = 0; i < 4; i++)
                rmax[i] = fmaxf(rmax[i], __shfl_xor_sync(0xffffffffu, rmax[i], off));

        float rsum[4] = {};
        #pragma unroll
        for (int i = 0; i < 4; i++) {
            float nm = fmaxf(m[i], rmax[i]);
            float alpha = __expf(m[i] - nm);
            m[i] = nm;
            l[i] *= alpha;
            #pragma unroll
            for (int j = 0; j < 4; j++) o[i][j] *= alpha;
            #pragma unroll
            for (int j = 0; j < 4; j++) {
                float p = __expf(s[i][j] - nm);
                ps[(ty * 4 + i) * Q_PITCH + tx * 4 + j] = p;
                rsum[i] += p;
            }
        }
        #pragma unroll
        for (int off = 1; off < 16; off <<= 1)
            #pragma unroll
            for (int i = 0; i < 4; i++)
                rsum[i] += __shfl_xor_sync(0xffffffffu, rsum[i], off);
        #pragma unroll
        for (int i = 0; i < 4; i++) l[i] += rsum[i];

        __syncthreads();

        #pragma unroll
        for (int k = 0; k < 64; k++) {
            float a[4];
            #pragma unroll
            for (int i = 0; i < 4; i++) a[i] = ps[(ty * 4 + i) * Q_PITCH + k];
            float4 bv = *(const float4*)&vs[k * 64 + tx * 4];
            #pragma unroll
            for (int i = 0; i < 4; i++) {
                o[i][0] += a[i] * bv.x; o[i][1] += a[i] * bv.y;
                o[i][2] += a[i] * bv.z; o[i][3] += a[i] * bv.w;
            }
        }
        __syncthreads();
    }

    float* Og = Out + ((size_t)b * SS + qb * 64) * HH;
    #pragma unroll
    for (int i = 0; i < 4; i++) {
        float inv = 1.0f / l[i];
        float4 v = make_float4(o[i][0] * inv, o[i][1] * inv,
                               o[i][2] * inv, o[i][3] * inv);
        *(float4*)(Og + (size_t)(ty * 4 + i) * HH + tx * 4) = v;
    }
}

// ---------------------------------------------------------------------------
extern "C" void kernel_launch(void* const* d_in, const int* in_sizes, int n_in,
                              void* d_out, int out_size)
{
    const float* x  = (const float*)d_in[0];
    const float* Wq = (const float*)d_in[1];
    const float* Wk = (const float*)d_in[2];
    const float* Wv = (const float*)d_in[3];
    float* out = (float*)d_out;
    (void)in_sizes; (void)n_in; (void)out_size;

    cudaFuncSetAttribute(attn_kernel, cudaFuncAttributeMaxDynamicSharedMemorySize,
                         ATTN_SMEM_BYTES);

    prep_w<<<768, 256>>>(Wq, Wk, Wv);
    qkv_mma<<<(BB * SS) / 128, 256>>>(x);
    attn_kernel<<<dim3(SS / 64, BB), 256, ATTN_SMEM_BYTES>>>(out);
}

// round 6
// speedup vs baseline: 1.7576x; 1.4516x over previous
#include <cuda_runtime.h>
#include <cuda_bf16.h>
#include <math.h>
#include <stdint.h>

#define BB 8
#define SS 2048
#define DD 1024
#define HH 64

// Scratch: Q,K,V projections [B*S, H] fp32; split weights [192][1024] bf16 hi/lo.
__device__ float g_Q[BB * SS * HH];
__device__ float g_K[BB * SS * HH];
__device__ float g_V[BB * SS * HH];
__device__ __nv_bfloat16 g_Bh[192 * 1024];
__device__ __nv_bfloat16 g_Bl[192 * 1024];

__device__ __forceinline__ uint32_t pack_bf2(float a, float b) {
    __nv_bfloat16 x = __float2bfloat16(a), y = __float2bfloat16(b);
    unsigned short xa = *(unsigned short*)&x, yb = *(unsigned short*)&y;
    return (uint32_t)xa | ((uint32_t)yb << 16);
}

// Split two fp32 into packed bf16 hi and packed bf16 lo (residual).
__device__ __forceinline__ void split2(float a, float b, uint32_t& hi, uint32_t& lo) {
    __nv_bfloat16 ha = __float2bfloat16(a), hb = __float2bfloat16(b);
    float ra = a - __bfloat162float(ha);
    float rb = b - __bfloat162float(hb);
    unsigned short va = *(unsigned short*)&ha, vb = *(unsigned short*)&hb;
    hi = (uint32_t)va | ((uint32_t)vb << 16);
    lo = pack_bf2(ra, rb);
}

// Fast exp2 for x <= 0 (clamped at -80): FMA/ALU pipes only, no MUFU, no cvt.
__device__ __forceinline__ float exp2_fast(float x) {
    x = fmaxf(x, -80.0f);
    float z = x + 12582912.0f;          // 1.5*2^23: RN gives round(x) in low bits
    float n = z - 12582912.0f;
    float f = x - n;                    // f in [-0.5, 0.5]
    float p =            1.3333558e-3f; // deg-5 Taylor of 2^f (err ~2e-6)
    p = fmaf(p, f, 9.6181291e-3f);
    p = fmaf(p, f, 5.5504109e-2f);
    p = fmaf(p, f, 2.4022650e-1f);
    p = fmaf(p, f, 6.9314718e-1f);
    p = fmaf(p, f, 1.0f);
    int e = __float_as_int(z);
    float sc = __int_as_float((e + (127 - 0x4B400000)) << 23);  // 2^round(x)
    return p * sc;
}

__device__ __forceinline__ void mma_bf16(float c[4],
                                         uint32_t a0, uint32_t a1, uint32_t a2, uint32_t a3,
                                         uint32_t b0, uint32_t b1) {
    asm volatile(
        "mma.sync.aligned.m16n8k16.row.col.f32.bf16.bf16.f32 "
        "{%0,%1,%2,%3}, {%4,%5,%6,%7}, {%8,%9}, {%0,%1,%2,%3};"
        : "+f"(c[0]), "+f"(c[1]), "+f"(c[2]), "+f"(c[3])
        : "r"(a0), "r"(a1), "r"(a2), "r"(a3), "r"(b0), "r"(b1));
}

__device__ __forceinline__ uint32_t lds32(const __nv_bfloat16* p) {
    return *(const uint32_t*)p;
}

// ---------------------------------------------------------------------------
// Kernel 0: split weights W[k][n] fp32 -> g_Bh/g_Bl[n_global][k] bf16.
// ---------------------------------------------------------------------------
__global__ void prep_w(const float* __restrict__ Wq,
                       const float* __restrict__ Wk,
                       const float* __restrict__ Wv)
{
    int i = blockIdx.x * blockDim.x + threadIdx.x;
    int n = i >> 10;
    int k = i & 1023;
    int m = n >> 6;
    int col = n & 63;
    const float* W = (m == 0) ? Wq : (m == 1) ? Wk : Wv;
    float w = W[k * 64 + col];
    __nv_bfloat16 h = __float2bfloat16(w);
    float lo = w - __bfloat162float(h);
    g_Bh[(size_t)n * 1024 + k] = h;
    g_Bl[(size_t)n * 1024 + k] = __float2bfloat16(lo);
}

// ---------------------------------------------------------------------------
// Kernel 1: QKV projection via mma.sync m16n8k16, 3-term hi/lo split.
// (unchanged from R5 passing version)
// ---------------------------------------------------------------------------
#define APITCH 36
#define BPITCH 36

__global__ __launch_bounds__(256) void qkv_mma(const float* __restrict__ x)
{
    __shared__ __align__(16) __nv_bfloat16 Ah[128 * APITCH];
    __shared__ __align__(16) __nv_bfloat16 Al[128 * APITCH];
    __shared__ __align__(16) __nv_bfloat16 Bh[192 * BPITCH];
    __shared__ __align__(16) __nv_bfloat16 Bl[192 * BPITCH];

    const int tid = threadIdx.x;
    const int wid = tid >> 5;
    const int lane = tid & 31;
    const int grow = lane >> 2;
    const int tg = lane & 3;
    const int warp_m = wid & 3;
    const int warp_n = wid >> 2;
    const int row0 = blockIdx.x * 128;

    float acc[2][12][4] = {};

    for (int k0 = 0; k0 < DD; k0 += 32) {
        #pragma unroll
        for (int i = 0; i < 4; i++) {
            int idx = tid + (i << 8);
            int r = idx >> 3;
            int c4 = idx & 7;
            float4 f = *(const float4*)(x + (size_t)(row0 + r) * DD + k0 + c4 * 4);
            uint32_t h01, l01, h23, l23;
            split2(f.x, f.y, h01, l01);
            split2(f.z, f.w, h23, l23);
            int off = r * APITCH + c4 * 4;
            *(uint2*)&Ah[off] = make_uint2(h01, h23);
            *(uint2*)&Al[off] = make_uint2(l01, l23);
        }
        #pragma unroll
        for (int i = 0; i < 3; i++) {
            int idx = tid + (i << 8);
            int r = idx >> 2;
            int q = idx & 3;
            int off = r * BPITCH + q * 8;
            uint4 vh = *(const uint4*)(g_Bh + (size_t)r * 1024 + k0 + q * 8);
            uint4 vl = *(const uint4*)(g_Bl + (size_t)r * 1024 + k0 + q * 8);
            *(uint2*)&Bh[off]     = make_uint2(vh.x, vh.y);
            *(uint2*)&Bh[off + 4] = make_uint2(vh.z, vh.w);
            *(uint2*)&Bl[off]     = make_uint2(vl.x, vl.y);
            *(uint2*)&Bl[off + 4] = make_uint2(vl.z, vl.w);
        }
        __syncthreads();

        #pragma unroll
        for (int ks = 0; ks < 2; ks++) {
            const int kofs = ks * 16 + tg * 2;
            uint32_t ah[2][4], al[2][4];
            #pragma unroll
            for (int mt = 0; mt < 2; mt++) {
                int rb = (warp_m * 32 + mt * 16 + grow) * APITCH + kofs;
                ah[mt][0] = lds32(Ah + rb);
                ah[mt][1] = lds32(Ah + rb + 8 * APITCH);
                ah[mt][2] = lds32(Ah + rb + 8);
                ah[mt][3] = lds32(Ah + rb + 8 * APITCH + 8);
                al[mt][0] = lds32(Al + rb);
                al[mt][1] = lds32(Al + rb + 8 * APITCH);
                al[mt][2] = lds32(Al + rb + 8);
                al[mt][3] = lds32(Al + rb + 8 * APITCH + 8);
            }
            #pragma unroll
            for (int nt = 0; nt < 12; nt++) {
                int cb = (warp_n * 96 + nt * 8 + grow) * BPITCH + kofs;
                uint32_t bh0 = lds32(Bh + cb);
                uint32_t bh1 = lds32(Bh + cb + 8);
                uint32_t bl0 = lds32(Bl + cb);
                uint32_t bl1 = lds32(Bl + cb + 8);
                #pragma unroll
                for (int mt = 0; mt < 2; mt++) {
                    mma_bf16(acc[mt][nt], ah[mt][0], ah[mt][1], ah[mt][2], ah[mt][3], bh0, bh1);
                    mma_bf16(acc[mt][nt], ah[mt][0], ah[mt][1], ah[mt][2], ah[mt][3], bl0, bl1);
                    mma_bf16(acc[mt][nt], al[mt][0], al[mt][1], al[mt][2], al[mt][3], bh0, bh1);
                }
            }
        }
        __syncthreads();
    }

    #pragma unroll
    for (int mt = 0; mt < 2; mt++) {
        int r = row0 + warp_m * 32 + mt * 16 + grow;
        #pragma unroll
        for (int nt = 0; nt < 12; nt++) {
            int col = warp_n * 96 + nt * 8 + tg * 2;
            int mat = col >> 6;
            int c = col & 63;
            float* dst = (mat == 0) ? g_Q : (mat == 1) ? g_K : g_V;
            *(float2*)(dst + (size_t)r * 64 + c) =
                make_float2(acc[mt][nt][0], acc[mt][nt][1]);
            *(float2*)(dst + (size_t)(r + 8) * 64 + c) =
                make_float2(acc[mt][nt][2], acc[mt][nt][3]);
        }
    }
}

// ---------------------------------------------------------------------------
// Kernel 2: causal flash attention on mma.sync (bf16 hi/lo split, fp32 acc).
// CTA = 128 threads (4 warps), Q tile = 64 rows (warp = 16 rows).
// S tile 64(q) x 64(k), head dim 64. P kept in registers (C-frag == A-frag).
// smem pitch 72 bf16 (144 B): frag LDS.32 conflict-free (bank = 4*grow+tg).
// ---------------------------------------------------------------------------
#define KPITCH 72
#define SCL 0.18033688011112042f   /* 0.125 * log2(e) */

__global__ __launch_bounds__(128) void attn_mma(float* __restrict__ Out)
{
    __shared__ __align__(16) __nv_bfloat16 Kh[64 * KPITCH];
    __shared__ __align__(16) __nv_bfloat16 Kl[64 * KPITCH];
    __shared__ __align__(16) __nv_bfloat16 Vth[64 * KPITCH];
    __shared__ __align__(16) __nv_bfloat16 Vtl[64 * KPITCH];

    const int tid = threadIdx.x;
    const int wm = tid >> 5;          // warp -> 16 q-rows
    const int lane = tid & 31;
    const int grow = lane >> 2;
    const int tg = lane & 3;
    const int qb = blockIdx.x;
    const int b  = blockIdx.y;

    const float* Qg = g_Q + (size_t)(b * SS + qb * 64 + wm * 16) * HH;
    const float* Kg = g_K + (size_t)b * SS * HH;
    const float* Vg = g_V + (size_t)b * SS * HH;

    // Hoist Q fragments (hi/lo bf16) into registers — constant over kb loop.
    uint32_t qh[4][4], ql[4][4];
    #pragma unroll
    for (int kt = 0; kt < 4; kt++) {
        float2 v00 = *(const float2*)(Qg + grow * HH + kt * 16 + tg * 2);
        float2 v10 = *(const float2*)(Qg + (grow + 8) * HH + kt * 16 + tg * 2);
        float2 v01 = *(const float2*)(Qg + grow * HH + kt * 16 + tg * 2 + 8);
        float2 v11 = *(const float2*)(Qg + (grow + 8) * HH + kt * 16 + tg * 2 + 8);
        split2(v00.x, v00.y, qh[kt][0], ql[kt][0]);
        split2(v10.x, v10.y, qh[kt][1], ql[kt][1]);
        split2(v01.x, v01.y, qh[kt][2], ql[kt][2]);
        split2(v11.x, v11.y, qh[kt][3], ql[kt][3]);
    }

    float o[8][4] = {};
    float m0 = -1e30f, m1 = -1e30f, l0 = 0.0f, l1 = 0.0f;
    const int qr0 = qb * 64 + wm * 16 + grow;

    for (int kb = 0; kb <= qb; kb++) {
        // ---- K tile [64 key][64 h] fp32 -> Kh/Kl bf16 (row-major, coalesced).
        #pragma unroll
        for (int i = 0; i < 8; i++) {
            int idx = tid + i * 128;
            int r = idx >> 4, c4 = idx & 15;
            float4 f = *(const float4*)(Kg + (size_t)(kb * 64 + r) * HH + c4 * 4);
            uint32_t h01, lo01, h23, lo23;
            split2(f.x, f.y, h01, lo01);
            split2(f.z, f.w, h23, lo23);
            int off = r * KPITCH + c4 * 4;
            *(uint2*)&Kh[off] = make_uint2(h01, h23);
            *(uint2*)&Kl[off] = make_uint2(lo01, lo23);
        }
        // ---- V tile transposed -> Vth/Vtl [h][key]. Lanes take distinct keys
        // so the scalar STS.16s hit distinct/mergeable banks.
        #pragma unroll
        for (int i = 0; i < 8; i++) {
            int idx = tid + i * 128;
            int r = idx & 63;            // key
            int hb = (idx >> 6) * 4;     // h base
            float4 f = *(const float4*)(Vg + (size_t)(kb * 64 + r) * HH + hb);
            float vv[4] = {f.x, f.y, f.z, f.w};
            #pragma unroll
            for (int j = 0; j < 4; j++) {
                __nv_bfloat16 hi = __float2bfloat16(vv[j]);
                __nv_bfloat16 lo = __float2bfloat16(vv[j] - __bfloat162float(hi));
                Vth[(hb + j) * KPITCH + r] = hi;
                Vtl[(hb + j) * KPITCH + r] = lo;
            }
        }
        __syncthreads();

        // ---- S = Q K^T (3-term split), fp32 accum.
        float s[8][4] = {};
        #pragma unroll
        for (int nt = 0; nt < 8; nt++) {
            #pragma unroll
            for (int kt = 0; kt < 4; kt++) {
                int cb = (nt * 8 + grow) * KPITCH + kt * 16 + tg * 2;
                uint32_t bh0 = lds32(Kh + cb), bh1 = lds32(Kh + cb + 8);
                uint32_t bl0 = lds32(Kl + cb), bl1 = lds32(Kl + cb + 8);
                mma_bf16(s[nt], qh[kt][0], qh[kt][1], qh[kt][2], qh[kt][3], bh0, bh1);
                mma_bf16(s[nt], qh[kt][0], qh[kt][1], qh[kt][2], qh[kt][3], bl0, bl1);
                mma_bf16(s[nt], ql[kt][0], ql[kt][1], ql[kt][2], ql[kt][3], bh0, bh1);
            }
        }

        // ---- scale into log2 domain + causal mask (diagonal tile only).
        if (kb == qb) {
            #pragma unroll
            for (int nt = 0; nt < 8; nt++) {
                int kc = kb * 64 + nt * 8 + tg * 2;
                s[nt][0] = (kc     > qr0)     ? -1e30f : s[nt][0] * SCL;
                s[nt][1] = (kc + 1 > qr0)     ? -1e30f : s[nt][1] * SCL;
                s[nt][2] = (kc     > qr0 + 8) ? -1e30f : s[nt][2] * SCL;
                s[nt][3] = (kc + 1 > qr0 + 8) ? -1e30f : s[nt][3] * SCL;
            }
        } else {
            #pragma unroll
            for (int nt = 0; nt < 8; nt++) {
                s[nt][0] *= SCL; s[nt][1] *= SCL;
                s[nt][2] *= SCL; s[nt][3] *= SCL;
            }
        }

        // ---- online softmax (base-2), quad reduction over tg lanes.
        float mx0 = -1e30f, mx1 = -1e30f;
        #pragma unroll
        for (int nt = 0; nt < 8; nt++) {
            mx0 = fmaxf(mx0, fmaxf(s[nt][0], s[nt][1]));
            mx1 = fmaxf(mx1, fmaxf(s[nt][2], s[nt][3]));
        }
        mx0 = fmaxf(mx0, __shfl_xor_sync(0xffffffffu, mx0, 1));
        mx0 = fmaxf(mx0, __shfl_xor_sync(0xffffffffu, mx0, 2));
        mx1 = fmaxf(mx1, __shfl_xor_sync(0xffffffffu, mx1, 1));
        mx1 = fmaxf(mx1, __shfl_xor_sync(0xffffffffu, mx1, 2));
        float nm0 = fmaxf(m0, mx0), nm1 = fmaxf(m1, mx1);
        float a0 = exp2_fast(m0 - nm0), a1 = exp2_fast(m1 - nm1);
        m0 = nm0; m1 = nm1;

        float rs0 = 0.0f, rs1 = 0.0f;
        #pragma unroll
        for (int nt = 0; nt < 8; nt++) {
            float p0 = exp2_fast(s[nt][0] - nm0);
            float p1 = exp2_fast(s[nt][1] - nm0);
            float p2 = exp2_fast(s[nt][2] - nm1);
            float p3 = exp2_fast(s[nt][3] - nm1);
            s[nt][0] = p0; s[nt][1] = p1; s[nt][2] = p2; s[nt][3] = p3;
            rs0 += p0 + p1;
            rs1 += p2 + p3;
        }
        rs0 += __shfl_xor_sync(0xffffffffu, rs0, 1);
        rs0 += __shfl_xor_sync(0xffffffffu, rs0, 2);
        rs1 += __shfl_xor_sync(0xffffffffu, rs1, 1);
        rs1 += __shfl_xor_sync(0xffffffffu, rs1, 2);
        l0 = l0 * a0 + rs0;
        l1 = l1 * a1 + rs1;
        #pragma unroll
        for (int nt = 0; nt < 8; nt++) {
            o[nt][0] *= a0; o[nt][1] *= a0;
            o[nt][2] *= a1; o[nt][3] *= a1;
        }

        // ---- O += P V (3-term split). P A-frags packed from S C-frags.
        #pragma unroll
        for (int kt = 0; kt < 4; kt++) {
            uint32_t ph[4], pl[4];
            split2(s[2 * kt][0],     s[2 * kt][1],     ph[0], pl[0]);
            split2(s[2 * kt][2],     s[2 * kt][3],     ph[1], pl[1]);
            split2(s[2 * kt + 1][0], s[2 * kt + 1][1], ph[2], pl[2]);
            split2(s[2 * kt + 1][2], s[2 * kt + 1][3], ph[3], pl[3]);
            #pragma unroll
            for (int nt = 0; nt < 8; nt++) {
                int cb = (nt * 8 + grow) * KPITCH + kt * 16 + tg * 2;
                uint32_t bh0 = lds32(Vth + cb), bh1 = lds32(Vth + cb + 8);
                uint32_t bl0 = lds32(Vtl + cb), bl1 = lds32(Vtl + cb + 8);
                mma_bf16(o[nt], ph[0], ph[1], ph[2], ph[3], bh0, bh1);
                mma_bf16(o[nt], ph[0], ph[1], ph[2], ph[3], bl0, bl1);
                mma_bf16(o[nt], pl[0], pl[1], pl[2], pl[3], bh0, bh1);
            }
        }
        __syncthreads();
    }

    // ---- epilogue
    float inv0 = 1.0f / l0, inv1 = 1.0f / l1;
    float* Og = Out + (size_t)(b * SS + qb * 64 + wm * 16) * HH;
    #pragma unroll
    for (int nt = 0; nt < 8; nt++) {
        *(float2*)(Og + grow * HH + nt * 8 + tg * 2) =
            make_float2(o[nt][0] * inv0, o[nt][1] * inv0);
        *(float2*)(Og + (grow + 8) * HH + nt * 8 + tg * 2) =
            make_float2(o[nt][2] * inv1, o[nt][3] * inv1);
    }
}

// ---------------------------------------------------------------------------
extern "C" void kernel_launch(void* const* d_in, const int* in_sizes, int n_in,
                              void* d_out, int out_size)
{
    const float* x  = (const float*)d_in[0];
    const float* Wq = (const float*)d_in[1];
    const float* Wk = (const float*)d_in[2];
    const float* Wv = (const float*)d_in[3];
    float* out = (float*)d_out;
    (void)in_sizes; (void)n_in; (void)out_size;

    prep_w<<<768, 256>>>(Wq, Wk, Wv);
    qkv_mma<<<(BB * SS) / 128, 256>>>(x);
    attn_mma<<<dim3(SS / 64, BB), 128>>>(out);
}

// round 7
// speedup vs baseline: 2.1884x; 1.2451x over previous
#include <cuda_runtime.h>
#include <cuda_bf16.h>
#include <math.h>
#include <stdint.h>

#define BB 8
#define SS 2048
#define DD 1024
#define HH 64

// Scratch.
__device__ float g_Q[BB * SS * HH];                 // fp32 Q
__device__ float g_V[BB * SS * HH];                 // fp32 V (input to prep_vt)
__device__ uint32_t g_Khp[BB * SS * 32];            // K hi, bf16x2 pairs along h
__device__ uint32_t g_Klp[BB * SS * 32];            // K lo
__device__ uint32_t g_Vthp[BB * 64 * 1024];         // V^T hi: [b][h][s/2] pairs along s
__device__ uint32_t g_Vtlp[BB * 64 * 1024];         // V^T lo
__device__ __nv_bfloat16 g_Bh[192 * 1024];          // weights hi  [n][k]
__device__ __nv_bfloat16 g_Bl[192 * 1024];          // weights lo

// ---------------------------------------------------------------------------
// Cheap truncation-based fp32 -> bf16 hi/lo split for a pair of floats.
// hi = top 16 bits (1 PRMT for both), lo = rn(x - hi) (1 cvt.bf16x2 for both).
// |hi - x| <= 2^-8|x|, residual captured to 2^-17|x| in lo.
// ---------------------------------------------------------------------------
__device__ __forceinline__ void tsplit2(float a, float b, uint32_t& hi, uint32_t& lo) {
    uint32_t ia = __float_as_uint(a), ib = __float_as_uint(b);
    hi = __byte_perm(ia, ib, 0x7632);               // [a.hi16 | b.hi16]
    float ra = a - __uint_as_float(ia & 0xFFFF0000u);
    float rb = b - __uint_as_float(ib & 0xFFFF0000u);
    asm("cvt.rn.bf16x2.f32 %0, %1, %2;" : "=r"(lo) : "f"(rb), "f"(ra));
}

// Fast exp2 for x <= 0 (clamped at -80): FMA/ALU pipes only, no MUFU.
__device__ __forceinline__ float exp2_fast(float x) {
    x = fmaxf(x, -80.0f);
    float z = x + 12582912.0f;
    float n = z - 12582912.0f;
    float f = x - n;
    float p =            1.3333558e-3f;
    p = fmaf(p, f, 9.6181291e-3f);
    p = fmaf(p, f, 5.5504109e-2f);
    p = fmaf(p, f, 2.4022650e-1f);
    p = fmaf(p, f, 6.9314718e-1f);
    p = fmaf(p, f, 1.0f);
    int e = __float_as_int(z);
    float sc = __int_as_float((e + (127 - 0x4B400000)) << 23);
    return p * sc;
}

__device__ __forceinline__ void mma_bf16(float c[4],
                                         uint32_t a0, uint32_t a1, uint32_t a2, uint32_t a3,
                                         uint32_t b0, uint32_t b1) {
    asm volatile(
        "mma.sync.aligned.m16n8k16.row.col.f32.bf16.bf16.f32 "
        "{%0,%1,%2,%3}, {%4,%5,%6,%7}, {%8,%9}, {%0,%1,%2,%3};"
        : "+f"(c[0]), "+f"(c[1]), "+f"(c[2]), "+f"(c[3])
        : "r"(a0), "r"(a1), "r"(a2), "r"(a3), "r"(b0), "r"(b1));
}

__device__ __forceinline__ uint32_t lds32(const __nv_bfloat16* p) {
    return *(const uint32_t*)p;
}

// ---------------------------------------------------------------------------
// Kernel 0: split weights W[k][n] fp32 -> g_Bh/g_Bl[n_global][k] bf16.
// ---------------------------------------------------------------------------
__global__ void prep_w(const float* __restrict__ Wq,
                       const float* __restrict__ Wk,
                       const float* __restrict__ Wv)
{
    int i = blockIdx.x * blockDim.x + threadIdx.x;
    int n = i >> 10;
    int k = i & 1023;
    int m = n >> 6;
    int col = n & 63;
    const float* W = (m == 0) ? Wq : (m == 1) ? Wk : Wv;
    float w = W[k * 64 + col];
    __nv_bfloat16 h = __float2bfloat16(w);
    float lo = w - __bfloat162float(h);
    g_Bh[(size_t)n * 1024 + k] = h;
    g_Bl[(size_t)n * 1024 + k] = __float2bfloat16(lo);
}

// ---------------------------------------------------------------------------
// Kernel 1: QKV projection via mma.sync m16n8k16, 3-term hi/lo split.
// Epilogue: Q,V -> fp32; K -> packed bf16 hi/lo pairs (pairs along h).
// ---------------------------------------------------------------------------
#define APITCH 36
#define BPITCH 36

__global__ __launch_bounds__(256) void qkv_mma(const float* __restrict__ x)
{
    __shared__ __align__(16) __nv_bfloat16 Ah[128 * APITCH];
    __shared__ __align__(16) __nv_bfloat16 Al[128 * APITCH];
    __shared__ __align__(16) __nv_bfloat16 Bh[192 * BPITCH];
    __shared__ __align__(16) __nv_bfloat16 Bl[192 * BPITCH];

    const int tid = threadIdx.x;
    const int wid = tid >> 5;
    const int lane = tid & 31;
    const int grow = lane >> 2;
    const int tg = lane & 3;
    const int warp_m = wid & 3;
    const int warp_n = wid >> 2;
    const int row0 = blockIdx.x * 128;

    float acc[2][12][4] = {};

    for (int k0 = 0; k0 < DD; k0 += 32) {
        #pragma unroll
        for (int i = 0; i < 4; i++) {
            int idx = tid + (i << 8);
            int r = idx >> 3;
            int c4 = idx & 7;
            float4 f = *(const float4*)(x + (size_t)(row0 + r) * DD + k0 + c4 * 4);
            uint32_t h01, l01, h23, l23;
            tsplit2(f.x, f.y, h01, l01);
            tsplit2(f.z, f.w, h23, l23);
            int off = r * APITCH + c4 * 4;
            *(uint2*)&Ah[off] = make_uint2(h01, h23);
            *(uint2*)&Al[off] = make_uint2(l01, l23);
        }
        #pragma unroll
        for (int i = 0; i < 3; i++) {
            int idx = tid + (i << 8);
            int r = idx >> 2;
            int q = idx & 3;
            int off = r * BPITCH + q * 8;
            uint4 vh = *(const uint4*)(g_Bh + (size_t)r * 1024 + k0 + q * 8);
            uint4 vl = *(const uint4*)(g_Bl + (size_t)r * 1024 + k0 + q * 8);
            *(uint2*)&Bh[off]     = make_uint2(vh.x, vh.y);
            *(uint2*)&Bh[off + 4] = make_uint2(vh.z, vh.w);
            *(uint2*)&Bl[off]     = make_uint2(vl.x, vl.y);
            *(uint2*)&Bl[off + 4] = make_uint2(vl.z, vl.w);
        }
        __syncthreads();

        #pragma unroll
        for (int ks = 0; ks < 2; ks++) {
            const int kofs = ks * 16 + tg * 2;
            uint32_t ah[2][4], al[2][4];
            #pragma unroll
            for (int mt = 0; mt < 2; mt++) {
                int rb = (warp_m * 32 + mt * 16 + grow) * APITCH + kofs;
                ah[mt][0] = lds32(Ah + rb);
                ah[mt][1] = lds32(Ah + rb + 8 * APITCH);
                ah[mt][2] = lds32(Ah + rb + 8);
                ah[mt][3] = lds32(Ah + rb + 8 * APITCH + 8);
                al[mt][0] = lds32(Al + rb);
                al[mt][1] = lds32(Al + rb + 8 * APITCH);
                al[mt][2] = lds32(Al + rb + 8);
                al[mt][3] = lds32(Al + rb + 8 * APITCH + 8);
            }
            #pragma unroll
            for (int nt = 0; nt < 12; nt++) {
                int cb = (warp_n * 96 + nt * 8 + grow) * BPITCH + kofs;
                uint32_t bh0 = lds32(Bh + cb);
                uint32_t bh1 = lds32(Bh + cb + 8);
                uint32_t bl0 = lds32(Bl + cb);
                uint32_t bl1 = lds32(Bl + cb + 8);
                #pragma unroll
                for (int mt = 0; mt < 2; mt++) {
                    mma_bf16(acc[mt][nt], ah[mt][0], ah[mt][1], ah[mt][2], ah[mt][3], bh0, bh1);
                    mma_bf16(acc[mt][nt], ah[mt][0], ah[mt][1], ah[mt][2], ah[mt][3], bl0, bl1);
                    mma_bf16(acc[mt][nt], al[mt][0], al[mt][1], al[mt][2], al[mt][3], bh0, bh1);
                }
            }
        }
        __syncthreads();
    }

    // Epilogue: Q,V fp32; K split once into bf16 hi/lo pair arrays.
    #pragma unroll
    for (int mt = 0; mt < 2; mt++) {
        int r = row0 + warp_m * 32 + mt * 16 + grow;
        #pragma unroll
        for (int nt = 0; nt < 12; nt++) {
            int col = warp_n * 96 + nt * 8 + tg * 2;
            int mat = col >> 6;
            int c = col & 63;
            if (mat == 1) {
                uint32_t h0, l0, h1, l1;
                tsplit2(acc[mt][nt][0], acc[mt][nt][1], h0, l0);
                tsplit2(acc[mt][nt][2], acc[mt][nt][3], h1, l1);
                int pidx = c >> 1;
                g_Khp[(size_t)r * 32 + pidx] = h0;
                g_Klp[(size_t)r * 32 + pidx] = l0;
                g_Khp[(size_t)(r + 8) * 32 + pidx] = h1;
                g_Klp[(size_t)(r + 8) * 32 + pidx] = l1;
            } else {
                float* dst = (mat == 0) ? g_Q : g_V;
                *(float2*)(dst + (size_t)r * 64 + c) =
                    make_float2(acc[mt][nt][0], acc[mt][nt][1]);
                *(float2*)(dst + (size_t)(r + 8) * 64 + c) =
                    make_float2(acc[mt][nt][2], acc[mt][nt][3]);
            }
        }
    }
}

// ---------------------------------------------------------------------------
// Kernel 1b: transpose + split V once: g_V [b][s][h] fp32 ->
// g_Vthp/g_Vtlp [b][h][s/2] packed bf16 pairs along s.
// Grid (SS/64, BB), 256 threads, 64x64 tile through smem.
// ---------------------------------------------------------------------------
__global__ __launch_bounds__(256) void prep_vt()
{
    __shared__ float vt[64 * 65];
    const int tid = threadIdx.x;
    const int s0 = blockIdx.x * 64;
    const int b  = blockIdx.y;

    #pragma unroll
    for (int i = 0; i < 4; i++) {
        int idx = tid + (i << 8);
        int r = idx >> 4;
        int c4 = (idx & 15) << 2;
        float4 f = *(const float4*)(g_V + (size_t)(b * SS + s0 + r) * 64 + c4);
        vt[r * 65 + c4 + 0] = f.x;  vt[r * 65 + c4 + 1] = f.y;
        vt[r * 65 + c4 + 2] = f.z;  vt[r * 65 + c4 + 3] = f.w;
    }
    __syncthreads();

    #pragma unroll
    for (int i = 0; i < 8; i++) {
        int idx = tid + (i << 8);        // 0..2047
        int h  = idx >> 5;               // 0..63
        int sp = idx & 31;               // pair index within tile
        float v0 = vt[(sp * 2 + 0) * 65 + h];
        float v1 = vt[(sp * 2 + 1) * 65 + h];
        uint32_t hi, lo;
        tsplit2(v0, v1, hi, lo);
        size_t o = (size_t)(b * 64 + h) * 1024 + (s0 >> 1) + sp;
        g_Vthp[o] = hi;
        g_Vtlp[o] = lo;
    }
}

// ---------------------------------------------------------------------------
// Kernel 2: causal flash attention on mma.sync.
// K/V smem fill = pure uint4 copies of precomputed bf16 hi/lo tiles.
// ---------------------------------------------------------------------------
#define KPITCH 72
#define SCL 0.18033688011112042f   /* 0.125 * log2(e) */

__global__ __launch_bounds__(128) void attn_mma(float* __restrict__ Out)
{
    __shared__ __align__(16) __nv_bfloat16 Kh[64 * KPITCH];
    __shared__ __align__(16) __nv_bfloat16 Kl[64 * KPITCH];
    __shared__ __align__(16) __nv_bfloat16 Vth[64 * KPITCH];
    __shared__ __align__(16) __nv_bfloat16 Vtl[64 * KPITCH];

    const int tid = threadIdx.x;
    const int wm = tid >> 5;
    const int lane = tid & 31;
    const int grow = lane >> 2;
    const int tg = lane & 3;
    const int qb = blockIdx.x;
    const int b  = blockIdx.y;

    const float* Qg = g_Q + (size_t)(b * SS + qb * 64 + wm * 16) * HH;

    // Hoist Q fragments (hi/lo) into registers.
    uint32_t qh[4][4], ql[4][4];
    #pragma unroll
    for (int kt = 0; kt < 4; kt++) {
        float2 v00 = *(const float2*)(Qg + grow * HH + kt * 16 + tg * 2);
        float2 v10 = *(const float2*)(Qg + (grow + 8) * HH + kt * 16 + tg * 2);
        float2 v01 = *(const float2*)(Qg + grow * HH + kt * 16 + tg * 2 + 8);
        float2 v11 = *(const float2*)(Qg + (grow + 8) * HH + kt * 16 + tg * 2 + 8);
        tsplit2(v00.x, v00.y, qh[kt][0], ql[kt][0]);
        tsplit2(v10.x, v10.y, qh[kt][1], ql[kt][1]);
        tsplit2(v01.x, v01.y, qh[kt][2], ql[kt][2]);
        tsplit2(v11.x, v11.y, qh[kt][3], ql[kt][3]);
    }

    float o[8][4] = {};
    float m0 = -1e30f, m1 = -1e30f, l0 = 0.0f, l1 = 0.0f;
    const int qr0 = qb * 64 + wm * 16 + grow;

    for (int kb = 0; kb <= qb; kb++) {
        // ---- K tile: uint4 copies (pairs along h), 16B-aligned rows.
        const uint4* Khg = (const uint4*)(g_Khp + (size_t)(b * SS + kb * 64) * 32);
        const uint4* Klg = (const uint4*)(g_Klp + (size_t)(b * SS + kb * 64) * 32);
        #pragma unroll
        for (int i = 0; i < 4; i++) {
            int idx = tid + (i << 7);    // 0..511
            int r = idx >> 3, q = idx & 7;
            *(uint4*)&Kh[r * KPITCH + q * 8] = Khg[r * 8 + q];
            *(uint4*)&Kl[r * KPITCH + q * 8] = Klg[r * 8 + q];
        }
        // ---- V^T tile: uint4 copies (pairs along key).
        const uint4* Vhg = (const uint4*)(g_Vthp + (size_t)b * 64 * 1024);
        const uint4* Vlg = (const uint4*)(g_Vtlp + (size_t)b * 64 * 1024);
        #pragma unroll
        for (int i = 0; i < 4; i++) {
            int idx = tid + (i << 7);
            int h = idx >> 3, q = idx & 7;
            *(uint4*)&Vth[h * KPITCH + q * 8] = Vhg[h * 256 + kb * 8 + q];
            *(uint4*)&Vtl[h * KPITCH + q * 8] = Vlg[h * 256 + kb * 8 + q];
        }
        __syncthreads();

        // ---- S = Q K^T (3-term split), fp32 accum.
        float s[8][4] = {};
        #pragma unroll
        for (int nt = 0; nt < 8; nt++) {
            #pragma unroll
            for (int kt = 0; kt < 4; kt++) {
                int cb = (nt * 8 + grow) * KPITCH + kt * 16 + tg * 2;
                uint32_t bh0 = lds32(Kh + cb), bh1 = lds32(Kh + cb + 8);
                uint32_t bl0 = lds32(Kl + cb), bl1 = lds32(Kl + cb + 8);
                mma_bf16(s[nt], qh[kt][0], qh[kt][1], qh[kt][2], qh[kt][3], bh0, bh1);
                mma_bf16(s[nt], qh[kt][0], qh[kt][1], qh[kt][2], qh[kt][3], bl0, bl1);
                mma_bf16(s[nt], ql[kt][0], ql[kt][1], ql[kt][2], ql[kt][3], bh0, bh1);
            }
        }

        // ---- scale into log2 domain + causal mask.
        if (kb == qb) {
            #pragma unroll
            for (int nt = 0; nt < 8; nt++) {
                int kc = kb * 64 + nt * 8 + tg * 2;
                s[nt][0] = (kc     > qr0)     ? -1e30f : s[nt][0] * SCL;
                s[nt][1] = (kc + 1 > qr0)     ? -1e30f : s[nt][1] * SCL;
                s[nt][2] = (kc     > qr0 + 8) ? -1e30f : s[nt][2] * SCL;
                s[nt][3] = (kc + 1 > qr0 + 8) ? -1e30f : s[nt][3] * SCL;
            }
        } else {
            #pragma unroll
            for (int nt = 0; nt < 8; nt++) {
                s[nt][0] *= SCL; s[nt][1] *= SCL;
                s[nt][2] *= SCL; s[nt][3] *= SCL;
            }
        }

        // ---- online softmax (base-2).
        float mx0 = -1e30f, mx1 = -1e30f;
        #pragma unroll
        for (int nt = 0; nt < 8; nt++) {
            mx0 = fmaxf(mx0, fmaxf(s[nt][0], s[nt][1]));
            mx1 = fmaxf(mx1, fmaxf(s[nt][2], s[nt][3]));
        }
        mx0 = fmaxf(mx0, __shfl_xor_sync(0xffffffffu, mx0, 1));
        mx0 = fmaxf(mx0, __shfl_xor_sync(0xffffffffu, mx0, 2));
        mx1 = fmaxf(mx1, __shfl_xor_sync(0xffffffffu, mx1, 1));
        mx1 = fmaxf(mx1, __shfl_xor_sync(0xffffffffu, mx1, 2));
        float nm0 = fmaxf(m0, mx0), nm1 = fmaxf(m1, mx1);
        float a0 = exp2_fast(m0 - nm0), a1 = exp2_fast(m1 - nm1);
        m0 = nm0; m1 = nm1;

        float rs0 = 0.0f, rs1 = 0.0f;
        #pragma unroll
        for (int nt = 0; nt < 8; nt++) {
            float p0 = exp2_fast(s[nt][0] - nm0);
            float p1 = exp2_fast(s[nt][1] - nm0);
            float p2 = exp2_fast(s[nt][2] - nm1);
            float p3 = exp2_fast(s[nt][3] - nm1);
            s[nt][0] = p0; s[nt][1] = p1; s[nt][2] = p2; s[nt][3] = p3;
            rs0 += p0 + p1;
            rs1 += p2 + p3;
        }
        rs0 += __shfl_xor_sync(0xffffffffu, rs0, 1);
        rs0 += __shfl_xor_sync(0xffffffffu, rs0, 2);
        rs1 += __shfl_xor_sync(0xffffffffu, rs1, 1);
        rs1 += __shfl_xor_sync(0xffffffffu, rs1, 2);
        l0 = l0 * a0 + rs0;
        l1 = l1 * a1 + rs1;
        #pragma unroll
        for (int nt = 0; nt < 8; nt++) {
            o[nt][0] *= a0; o[nt][1] *= a0;
            o[nt][2] *= a1; o[nt][3] *= a1;
        }

        // ---- O += P V (3-term split).
        #pragma unroll
        for (int kt = 0; kt < 4; kt++) {
            uint32_t ph[4], pl[4];
            tsplit2(s[2 * kt][0],     s[2 * kt][1],     ph[0], pl[0]);
            tsplit2(s[2 * kt][2],     s[2 * kt][3],     ph[1], pl[1]);
            tsplit2(s[2 * kt + 1][0], s[2 * kt + 1][1], ph[2], pl[2]);
            tsplit2(s[2 * kt + 1][2], s[2 * kt + 1][3], ph[3], pl[3]);
            #pragma unroll
            for (int nt = 0; nt < 8; nt++) {
                int cb = (nt * 8 + grow) * KPITCH + kt * 16 + tg * 2;
                uint32_t bh0 = lds32(Vth + cb), bh1 = lds32(Vth + cb + 8);
                uint32_t bl0 = lds32(Vtl + cb), bl1 = lds32(Vtl + cb + 8);
                mma_bf16(o[nt], ph[0], ph[1], ph[2], ph[3], bh0, bh1);
                mma_bf16(o[nt], ph[0], ph[1], ph[2], ph[3], bl0, bl1);
                mma_bf16(o[nt], pl[0], pl[1], pl[2], pl[3], bh0, bh1);
            }
        }
        __syncthreads();
    }

    float inv0 = 1.0f / l0, inv1 = 1.0f / l1;
    float* Og = Out + (size_t)(b * SS + qb * 64 + wm * 16) * HH;
    #pragma unroll
    for (int nt = 0; nt < 8; nt++) {
        *(float2*)(Og + grow * HH + nt * 8 + tg * 2) =
            make_float2(o[nt][0] * inv0, o[nt][1] * inv0);
        *(float2*)(Og + (grow + 8) * HH + nt * 8 + tg * 2) =
            make_float2(o[nt][2] * inv1, o[nt][3] * inv1);
    }
}

// ---------------------------------------------------------------------------
extern "C" void kernel_launch(void* const* d_in, const int* in_sizes, int n_in,
                              void* d_out, int out_size)
{
    const float* x  = (const float*)d_in[0];
    const float* Wq = (const float*)d_in[1];
    const float* Wk = (const float*)d_in[2];
    const float* Wv = (const float*)d_in[3];
    float* out = (float*)d_out;
    (void)in_sizes; (void)n_in; (void)out_size;

    prep_w<<<768, 256>>>(Wq, Wk, Wv);
    qkv_mma<<<(BB * SS) / 128, 256>>>(x);
    prep_vt<<<dim3(SS / 64, BB), 256>>>();
    attn_mma<<<dim3(SS / 64, BB), 128>>>(out);
}